// round 3
// baseline (speedup 1.0000x reference)
#include <cuda_runtime.h>
#include <math.h>

#define B_  2
#define L_  2048
#define C_  1024
#define H_  16
#define HD_ 64
#define G_  32
#define CG_ 32          // channels per group
#define N3C (3 * C_)
#define ML  (B_ * L_)   // 4096 rows

// ---------------- scratch (static device globals; no allocation allowed) ----------------
__device__ float g_stats[B_ * G_ * 2];          // mu, rstd per (b,g)
__device__ float g_xn[(size_t)ML * C_];         // normalized input      16 MB
__device__ float g_qkv[(size_t)ML * N3C];       // qkv projection        48 MB
__device__ float g_att[(size_t)ML * C_];        // attention output      16 MB

// ---------------- kernel 1: GroupNorm statistics ----------------
// grid = B*G = 64 blocks, 256 threads. Reduce over L*CG = 65536 elements.
__global__ void gn_stats_kernel(const float* __restrict__ x) {
    int bg = blockIdx.x;
    int b = bg / G_;
    int g = bg % G_;
    const float* xp = x + (size_t)b * L_ * C_ + g * CG_;

    float s = 0.f, s2 = 0.f;
    for (int i = threadIdx.x; i < L_ * CG_ / 4; i += 256) {
        int l = i >> 3;                 // 8 float4 per row of 32 ch
        int c4 = (i & 7) * 4;
        float4 v = *(const float4*)(xp + (size_t)l * C_ + c4);
        s  += v.x + v.y + v.z + v.w;
        s2 += v.x * v.x + v.y * v.y + v.z * v.z + v.w * v.w;
    }
    // warp reduce
    #pragma unroll
    for (int o = 16; o > 0; o >>= 1) {
        s  += __shfl_down_sync(0xFFFFFFFFu, s, o);
        s2 += __shfl_down_sync(0xFFFFFFFFu, s2, o);
    }
    __shared__ float sh[2][8];
    int w = threadIdx.x >> 5, ln = threadIdx.x & 31;
    if (ln == 0) { sh[0][w] = s; sh[1][w] = s2; }
    __syncthreads();
    if (w == 0) {
        s  = (ln < 8) ? sh[0][ln] : 0.f;
        s2 = (ln < 8) ? sh[1][ln] : 0.f;
        #pragma unroll
        for (int o = 4; o > 0; o >>= 1) {
            s  += __shfl_down_sync(0xFFFFFFFFu, s, o);
            s2 += __shfl_down_sync(0xFFFFFFFFu, s2, o);
        }
        if (ln == 0) {
            const float inv_n = 1.0f / (float)(L_ * CG_);
            float mu  = s * inv_n;
            float var = s2 * inv_n - mu * mu;
            g_stats[bg * 2 + 0] = mu;
            g_stats[bg * 2 + 1] = rsqrtf(var + 1e-6f);
        }
    }
}

// ---------------- kernel 2: apply GroupNorm ----------------
__global__ void gn_apply_kernel(const float* __restrict__ x,
                                const float* __restrict__ gamma,
                                const float* __restrict__ beta) {
    size_t i = (size_t)blockIdx.x * blockDim.x + threadIdx.x;  // float4 index
    size_t base = i * 4;
    if (base >= (size_t)ML * C_) return;
    int c  = (int)(base % C_);
    int bl = (int)(base / C_);
    int b  = bl >> 11;           // L_ = 2048
    int g  = c >> 5;
    float mu = g_stats[(b * G_ + g) * 2 + 0];
    float rs = g_stats[(b * G_ + g) * 2 + 1];
    float4 xv = *(const float4*)(x + base);
    float4 gv = *(const float4*)(gamma + c);
    float4 bv = *(const float4*)(beta + c);
    float4 r;
    r.x = (xv.x - mu) * rs * gv.x + bv.x;
    r.y = (xv.y - mu) * rs * gv.y + bv.y;
    r.z = (xv.z - mu) * rs * gv.z + bv.z;
    r.w = (xv.w - mu) * rs * gv.w + bv.w;
    *(float4*)(g_xn + base) = r;
}

// ---------------- kernel 3/5: tiled SGEMM 128x128x8, 256 threads, 8x8 per thread ----------------
// EPI 0: g_qkv = g_xn @ W + bias                       (QKV)
// EPI 1: out   = (x + g_att @ W + bias) * rsqrt(2)     (proj + residual)
template <int EPI>
__global__ __launch_bounds__(256) void sgemm_kernel(
    const float* __restrict__ W,
    const float* __restrict__ bias,
    const float* __restrict__ resid,    // x for EPI==1
    float* __restrict__ Dout,           // d_out for EPI==1 (else unused)
    int N, int K)
{
    const float* A = (EPI == 0) ? g_xn : g_att;
    float* Cout    = (EPI == 0) ? g_qkv : Dout;

    __shared__ float As[8][128];
    __shared__ float Bs[8][128];

    int tid = threadIdx.x;
    int bm = blockIdx.y * 128;
    int bn = blockIdx.x * 128;
    int tx = tid & 15;          // 0..15
    int ty = tid >> 4;          // 0..15

    float acc[8][8];
    #pragma unroll
    for (int i = 0; i < 8; i++)
        #pragma unroll
        for (int j = 0; j < 8; j++) acc[i][j] = 0.f;

    int arow = tid >> 1;              // 0..127
    int acol = (tid & 1) * 4;         // 0 or 4
    int brow = tid >> 5;              // 0..7
    int bcol = (tid & 31) * 4;        // 0..124

    const float* Aptr = A + (size_t)(bm + arow) * K + acol;
    const float* Bptr = W + (size_t)brow * N + bn + bcol;

    for (int k0 = 0; k0 < K; k0 += 8) {
        float4 av = *(const float4*)(Aptr + k0);
        float4 bv = *(const float4*)(Bptr + (size_t)k0 * N);
        As[acol + 0][arow] = av.x;
        As[acol + 1][arow] = av.y;
        As[acol + 2][arow] = av.z;
        As[acol + 3][arow] = av.w;
        *(float4*)&Bs[brow][bcol] = bv;
        __syncthreads();
        #pragma unroll
        for (int kk = 0; kk < 8; kk++) {
            float a[8], b[8];
            #pragma unroll
            for (int i = 0; i < 8; i++) a[i] = As[kk][ty * 8 + i];
            #pragma unroll
            for (int i = 0; i < 8; i++) b[i] = Bs[kk][tx * 8 + i];
            #pragma unroll
            for (int i = 0; i < 8; i++)
                #pragma unroll
                for (int j = 0; j < 8; j++)
                    acc[i][j] += a[i] * b[j];
        }
        __syncthreads();
    }

    const float rsqrt2 = 0.70710678118654752f;
    #pragma unroll
    for (int i = 0; i < 8; i++) {
        int row = bm + ty * 8 + i;
        #pragma unroll
        for (int j = 0; j < 8; j += 4) {
            int col = bn + tx * 8 + j;
            float4 bb = *(const float4*)(bias + col);
            float4 v;
            v.x = acc[i][j + 0] + bb.x;
            v.y = acc[i][j + 1] + bb.y;
            v.z = acc[i][j + 2] + bb.z;
            v.w = acc[i][j + 3] + bb.w;
            if (EPI == 1) {
                float4 rv = *(const float4*)(resid + (size_t)row * N + col);
                v.x = (v.x + rv.x) * rsqrt2;
                v.y = (v.y + rv.y) * rsqrt2;
                v.z = (v.z + rv.z) * rsqrt2;
                v.w = (v.w + rv.w) * rsqrt2;
            }
            *(float4*)(Cout + (size_t)row * N + col) = v;
        }
    }
}

// ---------------- kernel 4: flash attention (fp32) ----------------
// grid = (L/128, B*H), 128 threads. Thread i owns query row (blockIdx.x*128+i).
// q, o, and per-tile scores live in registers; K/V tiles (32 keys) in static smem (16 KB).
__global__ __launch_bounds__(128) void flash_kernel() {
    __shared__ float Ks[32 * 64];
    __shared__ float Vs[32 * 64];

    int bh = blockIdx.y;
    int b = bh >> 4;        // H_ = 16
    int h = bh & 15;
    int tid = threadIdx.x;
    int qrow = blockIdx.x * 128 + tid;

    const float* base = g_qkv + (size_t)b * L_ * N3C;
    const float* qptr = base + (size_t)qrow * N3C + h * (3 * HD_);
    const float* kbase = base + h * (3 * HD_) + HD_;
    const float* vbase = base + h * (3 * HD_) + 2 * HD_;

    float q[HD_];
    #pragma unroll
    for (int d4 = 0; d4 < HD_ / 4; d4++) {
        float4 t = *(const float4*)(qptr + d4 * 4);
        q[4 * d4 + 0] = t.x * 0.125f;   // 1/sqrt(64)
        q[4 * d4 + 1] = t.y * 0.125f;
        q[4 * d4 + 2] = t.z * 0.125f;
        q[4 * d4 + 3] = t.w * 0.125f;
    }
    float o[HD_];
    #pragma unroll
    for (int d = 0; d < HD_; d++) o[d] = 0.f;
    float m = -1e30f, l = 0.f;

    for (int kb = 0; kb < L_ / 32; kb++) {
        __syncthreads();
        // cooperative load of K/V tiles (32 rows x 64 cols), 4 float4 per thread each
        #pragma unroll
        for (int t = 0; t < 4; t++) {
            int idx = t * 128 + tid;        // float4 index 0..511
            int r = idx >> 4;               // row 0..31
            int c4 = (idx & 15) * 4;
            size_t goff = (size_t)(kb * 32 + r) * N3C + c4;
            *(float4*)&Ks[r * 64 + c4] = *(const float4*)(kbase + goff);
            *(float4*)&Vs[r * 64 + c4] = *(const float4*)(vbase + goff);
        }
        __syncthreads();

        // scores in registers: s_j = q . k_j  (broadcast reads of Ks)
        float s[32];
        #pragma unroll
        for (int j = 0; j < 32; j++) {
            float acc = 0.f;
            #pragma unroll
            for (int d = 0; d < HD_; d++) acc += q[d] * Ks[j * 64 + d];
            s[j] = acc;
        }
        float mnew = m;
        #pragma unroll
        for (int j = 0; j < 32; j++) mnew = fmaxf(mnew, s[j]);
        float corr = __expf(m - mnew);
        l *= corr;
        #pragma unroll
        for (int d = 0; d < HD_; d++) o[d] *= corr;
        #pragma unroll
        for (int j = 0; j < 32; j++) {
            float p = __expf(s[j] - mnew);
            l += p;
            #pragma unroll
            for (int d = 0; d < HD_; d++) o[d] += p * Vs[j * 64 + d];
        }
        m = mnew;
    }

    float inv = 1.f / l;
    float* op = g_att + (size_t)(b * L_ + qrow) * C_ + h * HD_;
    #pragma unroll
    for (int d4 = 0; d4 < HD_ / 4; d4++) {
        float4 t;
        t.x = o[4 * d4 + 0] * inv;
        t.y = o[4 * d4 + 1] * inv;
        t.z = o[4 * d4 + 2] * inv;
        t.w = o[4 * d4 + 3] * inv;
        *(float4*)(op + 4 * d4) = t;
    }
}

// ---------------- launcher ----------------
extern "C" void kernel_launch(void* const* d_in, const int* in_sizes, int n_in,
                              void* d_out, int out_size) {
    const float* x        = (const float*)d_in[0];
    const float* gn_scale = (const float*)d_in[1];
    const float* gn_bias  = (const float*)d_in[2];
    const float* qkv_w    = (const float*)d_in[3];
    const float* qkv_b    = (const float*)d_in[4];
    const float* proj_w   = (const float*)d_in[5];
    const float* proj_b   = (const float*)d_in[6];
    float* out = (float*)d_out;

    // 1) GroupNorm stats
    gn_stats_kernel<<<B_ * G_, 256>>>(x);

    // 2) apply GroupNorm
    {
        int total4 = ML * C_ / 4;
        gn_apply_kernel<<<(total4 + 255) / 256, 256>>>(x, gn_scale, gn_bias);
    }

    // 3) QKV GEMM: [4096,1024] x [1024,3072]
    {
        dim3 grid(N3C / 128, ML / 128);
        sgemm_kernel<0><<<grid, 256>>>(qkv_w, qkv_b, nullptr, nullptr, N3C, C_);
    }

    // 4) flash attention
    {
        dim3 grid(L_ / 128, B_ * H_);
        flash_kernel<<<grid, 128>>>();
    }

    // 5) proj GEMM + residual combine: out = (x + att@proj_w + proj_b) / sqrt(2)
    {
        dim3 grid(C_ / 128, ML / 128);
        sgemm_kernel<1><<<grid, 256>>>(proj_w, proj_b, x, out, C_, C_);
    }
}